// round 6
// baseline (speedup 1.0000x reference)
#include <cuda_runtime.h>
#include <cstdint>

// Problem constants (fixed by the dataset)
#define T_LEN 4096
#define B_SZ  32
#define C_SZ  300
#define W_SZ  128
#define C4    (C_SZ / 4)     // 75 float4 per (t,b) row
#define ROW4  (B_SZ * C4)    // 2400 float4 per t-slice
#define NTHR  480            // 2400 = 480 * 5 exactly
#define UNROLL 5

// One block per t. x is prefetched into SMEM via cp.async (no destination
// registers), fully overlapping the segment-scan prologue with the DRAM
// misses. Each thread consumes exactly the elements it copied, so only a
// per-thread cp.async.wait is needed for the staged data; __syncthreads
// covers s_pos only.
__global__ void __launch_bounds__(NTHR) k_fused(const float4* __restrict__ x,
                                                const float4* __restrict__ pe,
                                                const int*    __restrict__ dur,
                                                float4*       __restrict__ out) {
    __shared__ int    s_pos[B_SZ];
    __shared__ float4 stage[ROW4];            // 38.4 KB
    const int t    = blockIdx.x;
    const int warp = threadIdx.x >> 5;
    const int lane = threadIdx.x & 31;
    const int tid  = threadIdx.x;

    const float4* xrow = x + (size_t)t * ROW4;
    float4*       orow = out + (size_t)t * ROW4;

    // ---- issue 5 register-free streaming prefetches immediately ----
#pragma unroll
    for (int i = 0; i < UNROLL; i++) {
        int j = tid + i * NTHR;
        uint32_t sa = (uint32_t)__cvta_generic_to_shared(&stage[j]);
        asm volatile("cp.async.cg.shared.global [%0], [%1], 16;"
                     :: "r"(sa), "l"(xrow + j) : "memory");
    }
    asm volatile("cp.async.commit_group;" ::: "memory");

    // ---- prologue: segment position, overlapped with prefetch ----
    if (warp < 8) {
#pragma unroll
        for (int k = 0; k < 4; k++) {
            const int b = warp * 4 + k;
            int4 d4 = *(const int4*)(dur + b * W_SZ + lane * 4);
            int s = d4.x + d4.y + d4.z + d4.w;
            int incl = s;
#pragma unroll
            for (int o = 1; o < 32; o <<= 1) {
                int vv = __shfl_up_sync(0xffffffffu, incl, o);
                if (lane >= o) incl += vv;
            }
            int base = incl - s;                   // exclusive prefix across lanes
            int st0 = base;
            int st1 = base + d4.x;
            int st2 = st1 + d4.y;
            int st3 = st2 + d4.z;
            int tot = __shfl_sync(0xffffffffu, incl, 31);

            // Largest start <= t: starts nondecreasing across lanes.
            unsigned m = __ballot_sync(0xffffffffu, st0 <= t);
            int L = 31 - __clz(m);
            int loc = st0;
            if (st1 <= t) loc = st1;
            if (st2 <= t) loc = st2;
            if (st3 <= t) loc = st3;
            int seg = __shfl_sync(0xffffffffu, loc, L);

            if (lane == 0) s_pos[b] = (t < tot) ? (t - seg) : -1;
        }
    }
    __syncthreads();                              // publish s_pos

    // ---- wait for own staged data, then add pe and store ----
    asm volatile("cp.async.wait_group 0;" ::: "memory");

#pragma unroll
    for (int i = 0; i < UNROLL; i++) {
        int j  = tid + i * NTHR;
        int b  = j / C4;                          // constant divide -> mul/shift
        int c4 = j - b * C4;
        float4 v = stage[j];
        int p = s_pos[b];
        if (p >= 0) {
            float4 pv = __ldg(pe + p * C4 + c4);  // 6 MB table: L2-resident
            v.x += pv.x; v.y += pv.y; v.z += pv.z; v.w += pv.w;
        }
        __stcs(orow + j, v);                      // streaming write
    }
}

extern "C" void kernel_launch(void* const* d_in, const int* in_sizes, int n_in,
                              void* d_out, int out_size) {
    const float* x  = (const float*)d_in[0];
    const float* pe = (const float*)d_in[1];
    const int*   du = (const int*)d_in[2];
    // d_in[3] = train flag, unused by the reference math.
    k_fused<<<T_LEN, NTHR>>>((const float4*)x, (const float4*)pe, du, (float4*)d_out);
}